// round 15
// baseline (speedup 1.0000x reference)
#include <cuda_runtime.h>
#include <cuda_fp16.h>
#include <math.h>
#include <stdint.h>

#define DIM   256
#define MAXN  100000
#define MAXE  500000
#define BCAP  64

// ---------------- scratch ---------------------------------------------------
__device__ __half g_vh[(size_t)MAXN * DIM];     // v in fp16
__device__ __half g_combh[(size_t)MAXN * DIM];  // NORMALIZED comb in fp16
__device__ __half g_ph[(size_t)MAXN * DIM];     // prev in fp16 (A operand image)
__device__ float  g_bq[MAXN];
__device__ __half g_bh_v[DIM * DIM];            // Wk^T as fp16, [k][n]
__device__ __half g_bh_g[2 * DIM * DIM];        // Wg   as fp16, [k][n]
__device__ int    g_cnt[MAXN];
__device__ int    g_bucket[(size_t)MAXN * BCAP];
__device__ int    g_ovf[MAXE];
__device__ int    g_ovf_cnt;

// ---------------- helpers ---------------------------------------------------
__device__ __forceinline__ uint32_t smem_u32(const void* p) {
    uint32_t a;
    asm("{ .reg .u64 t; cvta.to.shared.u64 t, %1; cvt.u32.u64 %0, t; }" : "=r"(a) : "l"(p));
    return a;
}
__device__ __forceinline__ void cp_async16(uint32_t saddr, const void* gaddr) {
    asm volatile("cp.async.ca.shared.global [%0], [%1], 16;\n" :: "r"(saddr), "l"(gaddr));
}
__device__ __forceinline__ void cp_commit() {
    asm volatile("cp.async.commit_group;\n");
}
__device__ __forceinline__ void ldsm_x4(uint32_t r[4], uint32_t addr) {
    asm volatile("ldmatrix.sync.aligned.m8n8.x4.shared.b16 {%0,%1,%2,%3}, [%4];"
                 : "=r"(r[0]), "=r"(r[1]), "=r"(r[2]), "=r"(r[3]) : "r"(addr));
}
__device__ __forceinline__ void ldsm_x4_t(uint32_t r[4], uint32_t addr) {
    asm volatile("ldmatrix.sync.aligned.m8n8.x4.trans.shared.b16 {%0,%1,%2,%3}, [%4];"
                 : "=r"(r[0]), "=r"(r[1]), "=r"(r[2]), "=r"(r[3]) : "r"(addr));
}
__device__ __forceinline__ void mma_f16(float c[4], const uint32_t a[4], uint32_t b0, uint32_t b1) {
    asm volatile(
        "mma.sync.aligned.m16n8k16.row.col.f32.f16.f16.f32 "
        "{%0,%1,%2,%3}, {%4,%5,%6,%7}, {%8,%9}, {%0,%1,%2,%3};"
        : "+f"(c[0]), "+f"(c[1]), "+f"(c[2]), "+f"(c[3])
        : "r"(a[0]), "r"(a[1]), "r"(a[2]), "r"(a[3]), "r"(b0), "r"(b1));
}

// ---------------- prep kernels -----------------------------------------------
__global__ void k_h_wkT(const float* __restrict__ Wk, __half* __restrict__ dst) {
    __shared__ float t[32][33];
    int bk = blockIdx.x * 32, bn = blockIdx.y * 32;
    int tx = threadIdx.x, ty = threadIdx.y;
    #pragma unroll
    for (int i = 0; i < 32; i += 8)
        t[ty + i][tx] = Wk[(bn + ty + i) * DIM + bk + tx];
    __syncthreads();
    #pragma unroll
    for (int i = 0; i < 32; i += 8)
        dst[(size_t)(bk + ty + i) * DIM + bn + tx] = __float2half(t[tx][ty + i]);
}
__global__ void k_h_wg(const float* __restrict__ Wg, __half* __restrict__ dst, int N) {
    int i = blockIdx.x * blockDim.x + threadIdx.x;
    if (i < 2 * DIM * DIM) dst[i] = __float2half(Wg[i]);
    if (i < N) g_cnt[i] = 0;
    if (i == 0) g_ovf_cnt = 0;
}
// prev fp32 -> fp16 image (one thread per 8 elements)
__global__ void k_h_prev(const float* __restrict__ prev, __half* __restrict__ dst, int total8) {
    int i = blockIdx.x * blockDim.x + threadIdx.x;
    if (i >= total8) return;
    const float4* p = (const float4*)prev + (size_t)2 * i;
    float4 a = __ldcs(p), b = __ldcs(p + 1);
    __half2 h0 = __floats2half2_rn(a.x, a.y);
    __half2 h1 = __floats2half2_rn(a.z, a.w);
    __half2 h2 = __floats2half2_rn(b.x, b.y);
    __half2 h3 = __floats2half2_rn(b.z, b.w);
    uint4 o = make_uint4(*(uint32_t*)&h0, *(uint32_t*)&h1, *(uint32_t*)&h2, *(uint32_t*)&h3);
    ((uint4*)dst)[i] = o;
}

// ---------------- bucketing --------------------------------------------------
__global__ void k_bucket(const int* __restrict__ idx, int E) {
    int e = blockIdx.x * blockDim.x + threadIdx.x;
    if (e >= E) return;
    int n = __ldg(idx + e);
    int r = atomicAdd(&g_cnt[n], 1);
    if (r < BCAP) g_bucket[(size_t)n * BCAP + r] = e;
    else          g_ovf[atomicAdd(&g_ovf_cnt, 1)] = e;
}

// ---------------- edge phase: warp/node, normalize-early, fp16 store ---------
__global__ __launch_bounds__(256) void k_edge_n(const float* __restrict__ x,
                                                const int* __restrict__ idx, int N) {
    int warp = threadIdx.x >> 5, lane = threadIdx.x & 31;
    int n = blockIdx.x * 8 + warp;
    if (n >= N) return;

    int c_full = g_cnt[n];
    int c = c_full < BCAP ? c_full : BCAP;
    uint2* cbh0 = (uint2*)(g_combh + (size_t)n * DIM + (size_t)lane * 4);
    uint2* cbh1 = (uint2*)(g_combh + (size_t)n * DIM + 128 + (size_t)lane * 4);

    if (c_full == 0) {
        uint2 z = make_uint2(0u, 0u);
        *cbh0 = z; *cbh1 = z;
        return;
    }

    const uint2* vp = (const uint2*)(g_vh + (size_t)n * DIM);
    uint2 h0 = vp[lane], h1 = vp[lane + 32];
    float2 v0 = __half22float2(*(__half2*)&h0.x);
    float2 v1 = __half22float2(*(__half2*)&h0.y);
    float2 v2 = __half22float2(*(__half2*)&h1.x);
    float2 v3 = __half22float2(*(__half2*)&h1.y);
    float bqn = g_bq[n];

    const int* bkt = g_bucket + (size_t)n * BCAP;
    int e = __ldg(bkt);
    const float4* xp = (const float4*)(x + (size_t)e * DIM);
    float4 a0 = __ldcs(xp + lane);
    float4 a1 = __ldcs(xp + lane + 32);

    float den = 0.f;
    float4 acc0 = make_float4(0.f, 0.f, 0.f, 0.f);
    float4 acc1 = make_float4(0.f, 0.f, 0.f, 0.f);

    for (int j = 0; j < c; j++) {
        float4 b0, b1;
        if (j + 1 < c) {
            int e2 = __ldg(bkt + j + 1);
            const float4* xp2 = (const float4*)(x + (size_t)e2 * DIM);
            b0 = __ldcs(xp2 + lane);
            b1 = __ldcs(xp2 + lane + 32);
        }
        float s = a0.x * v0.x + a0.y * v0.y + a0.z * v1.x + a0.w * v1.y
                + a1.x * v2.x + a1.y * v2.y + a1.z * v3.x + a1.w * v3.y;
        #pragma unroll
        for (int o = 16; o; o >>= 1) s += __shfl_xor_sync(0xffffffffu, s, o);
        float ex = expf((s + bqn) * 0.0625f);
        den += ex;
        acc0.x += ex * a0.x; acc0.y += ex * a0.y; acc0.z += ex * a0.z; acc0.w += ex * a0.w;
        acc1.x += ex * a1.x; acc1.y += ex * a1.y; acc1.z += ex * a1.z; acc1.w += ex * a1.w;
        a0 = b0; a1 = b1;
    }

    if (c_full > BCAP) {
        int t = g_ovf_cnt;
        for (int i = 0; i < t; i++) {
            int e2 = g_ovf[i];
            if (__ldg(idx + e2) != n) continue;
            const float4* xp2 = (const float4*)(x + (size_t)e2 * DIM);
            float4 c0 = xp2[lane], c1 = xp2[lane + 32];
            float s = c0.x * v0.x + c0.y * v0.y + c0.z * v1.x + c0.w * v1.y
                    + c1.x * v2.x + c1.y * v2.y + c1.z * v3.x + c1.w * v3.y;
            #pragma unroll
            for (int o = 16; o; o >>= 1) s += __shfl_xor_sync(0xffffffffu, s, o);
            float ex = expf((s + bqn) * 0.0625f);
            den += ex;
            acc0.x += ex * c0.x; acc0.y += ex * c0.y; acc0.z += ex * c0.z; acc0.w += ex * c0.w;
            acc1.x += ex * c1.x; acc1.y += ex * c1.y; acc1.z += ex * c1.z; acc1.w += ex * c1.w;
        }
    }

    float inv = 1.f / fmaxf(den, 1e-9f);
    __half2 p0 = __floats2half2_rn(acc0.x * inv, acc0.y * inv);
    __half2 p1 = __floats2half2_rn(acc0.z * inv, acc0.w * inv);
    __half2 p2 = __floats2half2_rn(acc1.x * inv, acc1.y * inv);
    __half2 p3 = __floats2half2_rn(acc1.z * inv, acc1.w * inv);
    *cbh0 = make_uint2(*(uint32_t*)&p0, *(uint32_t*)&p1);
    *cbh1 = make_uint2(*(uint32_t*)&p2, *(uint32_t*)&p3);
}

// ---------------- fp16 tensor-core GEMM: all-cp.async A, 3 CTAs/SM -----------
#define BM 64
#define BN 256
#define BK 32
#define ASTRH 40
#define BSTRH 264

template<int KT, bool GATE>
__global__ __launch_bounds__(256, 3) void k_gemm_h(const float* __restrict__ Aprev,
                                                   const float* __restrict__ bias,
                                                   float* __restrict__ out, int M) {
    __shared__ __half As[2][BM * ASTRH];
    __shared__ __half Bs[2][BK * BSTRH];
    __shared__ float  bks[DIM];

    const int tid  = threadIdx.x;
    const int lane = tid & 31;
    const int g    = lane >> 2;
    const int tg   = lane & 3;
    const int wid  = tid >> 5;
    const int wR   = (wid & 1) * 32;
    const int wCat = (wid >> 1) * 8;
    const int bm   = blockIdx.x * BM;
    const int lj   = lane >> 3;
    const int lr   = lane & 7;

    if (tid < 64) *(float4*)&bks[tid * 4] = *(const float4*)(bias + tid * 4);
    __syncthreads();

    float c[2][8][4];
    #pragma unroll
    for (int mi = 0; mi < 2; mi++)
        #pragma unroll
        for (int ni = 0; ni < 8; ni++)
            #pragma unroll
            for (int q = 0; q < 4; q++) c[mi][ni][q] = 0.f;

    // A stage: pure cp.async from fp16 image (g_ph or g_combh)
    auto stage = [&](int it, int buf) {
        const __half* asrc; int k0;
        if (GATE) {
            if (it < 8) { asrc = (const __half*)g_combh; k0 = it * 32; }
            else        { asrc = (const __half*)g_ph;    k0 = (it - 8) * 32; }
        } else {
            asrc = (const __half*)g_ph; k0 = it * 32;
        }
        {   // A: 64 rows x 32 halves = 256 x 16B, one per thread
            int row = tid >> 2, c8 = (tid & 3) * 8;
            int gr = bm + row; if (gr >= M) gr = M - 1;
            cp_async16(smem_u32(&As[buf][row * ASTRH + c8]),
                       asrc + (size_t)gr * DIM + k0 + c8);
        }
        const __half* bh = GATE ? (const __half*)g_bh_g : (const __half*)g_bh_v;
        int kb = GATE ? (it < 8 ? 256 + it * 32 : (it - 8) * 32) : it * 32;
        #pragma unroll
        for (int j = 0; j < 4; j++) {
            int seg = tid + j * 256;
            int kr = seg >> 5, c8 = (seg & 31) * 8;
            cp_async16(smem_u32(&Bs[buf][kr * BSTRH + c8]),
                       bh + (size_t)(kb + kr) * DIM + c8);
        }
        cp_commit();
    };

    stage(0, 0);

    float bqacc = 0.f;
    const int bq_row = tid >> 2;
    const int bq_q   = tid & 3;

    #pragma unroll 1
    for (int it = 0; it < KT; it++) {
        int buf = it & 1;
        if (it + 1 < KT) {
            stage(it + 1, (it + 1) & 1);
            asm volatile("cp.async.wait_group 1;\n" ::: "memory");
        } else {
            asm volatile("cp.async.wait_group 0;\n" ::: "memory");
        }
        __syncthreads();

        const __half* Ab = As[buf];
        const __half* Bb = Bs[buf];
        #pragma unroll
        for (int ks = 0; ks < BK; ks += 16) {
            uint32_t a[2][4];
            #pragma unroll
            for (int mi = 0; mi < 2; mi++) {
                uint32_t ad = smem_u32(&Ab[(wR + mi * 16 + (lj & 1) * 8 + lr) * ASTRH
                                           + ks + (lj >> 1) * 8]);
                ldsm_x4(a[mi], ad);
            }
            #pragma unroll
            for (int nn = 0; nn < 4; nn++) {
                uint32_t b[4];
                uint32_t bd = smem_u32(&Bb[(ks + (lj & 1) * 8 + lr) * BSTRH
                                           + (wCat + nn * 2 + (lj >> 1)) * 8]);
                ldsm_x4_t(b, bd);
                #pragma unroll
                for (int mi = 0; mi < 2; mi++) {
                    mma_f16(c[mi][nn * 2 + 0], a[mi], b[0], b[1]);
                    mma_f16(c[mi][nn * 2 + 1], a[mi], b[2], b[3]);
                }
            }
        }

        if (!GATE) {
            float s = 0.f;
            #pragma unroll
            for (int j = 0; j < 8; j++)
                s += __half2float(Ab[bq_row * ASTRH + bq_q * 8 + j])
                   * bks[it * 32 + bq_q * 8 + j];
            bqacc += s;
        }
        __syncthreads();
    }

    if (!GATE) {
        bqacc += __shfl_xor_sync(0xffffffffu, bqacc, 1);
        bqacc += __shfl_xor_sync(0xffffffffu, bqacc, 2);
        if (bq_q == 0 && bm + bq_row < M) g_bq[bm + bq_row] = bqacc;
    }

    #pragma unroll
    for (int mi = 0; mi < 2; mi++) {
        #pragma unroll
        for (int half = 0; half < 2; half++) {
            int r = bm + wR + mi * 16 + g + half * 8;
            if (r >= M) continue;
            #pragma unroll
            for (int ni = 0; ni < 8; ni++) {
                int cc = wCat * 8 + ni * 8 + tg * 2;
                float v0 = c[mi][ni][half * 2 + 0];
                float v1 = c[mi][ni][half * 2 + 1];
                if (GATE) {
                    float2 pv = *(const float2*)(Aprev + (size_t)r * DIM + cc);
                    uint32_t ch = *(const uint32_t*)(g_combh + (size_t)r * DIM + cc);
                    float2 cv = __half22float2(*(__half2*)&ch);
                    float g0 = 1.f / (1.f + expf(-(v0 + bks[cc])));
                    float g1 = 1.f / (1.f + expf(-(v1 + bks[cc + 1])));
                    float2 o;
                    o.x = g0 * pv.x + (1.f - g0) * cv.x;
                    o.y = g1 * pv.y + (1.f - g1) * cv.y;
                    *(float2*)(out + (size_t)r * DIM + cc) = o;
                } else {
                    __half2 hv = __floats2half2_rn(v0, v1);
                    *(uint32_t*)(g_vh + (size_t)r * DIM + cc) = *(uint32_t*)&hv;
                }
            }
        }
    }
}

// ---------------- launch ------------------------------------------------------
extern "C" void kernel_launch(void* const* d_in, const int* in_sizes, int n_in,
                              void* d_out, int out_size) {
    const float* x    = (const float*)d_in[0];
    const float* prev = (const float*)d_in[1];
    const float* Wk   = (const float*)d_in[2];
    const float* bk   = (const float*)d_in[3];
    const float* Wg   = (const float*)d_in[4];
    const float* bg   = (const float*)d_in[5];
    const int*   idx  = (const int*)d_in[6];
    float* out = (float*)d_out;

    int Dv = in_sizes[3];            // 256
    int E  = in_sizes[0] / Dv;
    int N  = in_sizes[1] / Dv;

    __half* bhv = nullptr; cudaGetSymbolAddress((void**)&bhv, g_bh_v);
    __half* bhg = nullptr; cudaGetSymbolAddress((void**)&bhg, g_bh_g);
    __half* ph  = nullptr; cudaGetSymbolAddress((void**)&ph,  g_ph);
    k_h_wkT<<<dim3(8, 8), dim3(32, 8)>>>(Wk, bhv);
    k_h_wg<<<(2 * DIM * DIM + 255) / 256, 256>>>(Wg, bhg, N);
    int total8 = N * (DIM / 8);
    k_h_prev<<<(total8 + 255) / 256, 256>>>(prev, ph, total8);
    k_bucket<<<(E + 255) / 256, 256>>>(idx, E);

    int gb = (N + BM - 1) / BM;
    k_gemm_h<8, false><<<gb, 256>>>(prev, bk, nullptr, N);

    k_edge_n<<<(N + 7) / 8, 256>>>(x, idx, N);

    k_gemm_h<16, true><<<gb, 256>>>(prev, bg, out, N);
}

// round 16
// speedup vs baseline: 1.1498x; 1.1498x over previous
#include <cuda_runtime.h>
#include <cuda_fp16.h>
#include <math.h>
#include <stdint.h>

#define DIM   256
#define MAXN  100000
#define MAXE  500000
#define BCAP  64

// ---------------- scratch ---------------------------------------------------
__device__ __half g_vh[(size_t)MAXN * DIM];     // v in fp16
__device__ __half g_combh[(size_t)MAXN * DIM];  // NORMALIZED comb in fp16
__device__ __half g_ph[(size_t)MAXN * DIM];     // prev in fp16 (A operand image)
__device__ float  g_bq[MAXN];
__device__ __half g_bh_v[DIM * DIM];            // Wk^T as fp16, [k][n]
__device__ __half g_bh_g[2 * DIM * DIM];        // Wg   as fp16, [k][n]
__device__ int    g_cnt[MAXN];
__device__ int    g_bucket[(size_t)MAXN * BCAP];
__device__ int    g_ovf[MAXE];
__device__ int    g_ovf_cnt;

// ---------------- helpers ---------------------------------------------------
__device__ __forceinline__ uint32_t smem_u32(const void* p) {
    uint32_t a;
    asm("{ .reg .u64 t; cvta.to.shared.u64 t, %1; cvt.u32.u64 %0, t; }" : "=r"(a) : "l"(p));
    return a;
}
__device__ __forceinline__ void cp_async16(uint32_t saddr, const void* gaddr) {
    asm volatile("cp.async.ca.shared.global [%0], [%1], 16;\n" :: "r"(saddr), "l"(gaddr));
}
__device__ __forceinline__ void cp_commit() {
    asm volatile("cp.async.commit_group;\n");
}
__device__ __forceinline__ void ldsm_x4(uint32_t r[4], uint32_t addr) {
    asm volatile("ldmatrix.sync.aligned.m8n8.x4.shared.b16 {%0,%1,%2,%3}, [%4];"
                 : "=r"(r[0]), "=r"(r[1]), "=r"(r[2]), "=r"(r[3]) : "r"(addr));
}
__device__ __forceinline__ void ldsm_x4_t(uint32_t r[4], uint32_t addr) {
    asm volatile("ldmatrix.sync.aligned.m8n8.x4.trans.shared.b16 {%0,%1,%2,%3}, [%4];"
                 : "=r"(r[0]), "=r"(r[1]), "=r"(r[2]), "=r"(r[3]) : "r"(addr));
}
__device__ __forceinline__ void mma_f16(float c[4], const uint32_t a[4], uint32_t b0, uint32_t b1) {
    asm volatile(
        "mma.sync.aligned.m16n8k16.row.col.f32.f16.f16.f32 "
        "{%0,%1,%2,%3}, {%4,%5,%6,%7}, {%8,%9}, {%0,%1,%2,%3};"
        : "+f"(c[0]), "+f"(c[1]), "+f"(c[2]), "+f"(c[3])
        : "r"(a[0]), "r"(a[1]), "r"(a[2]), "r"(a[3]), "r"(b0), "r"(b1));
}

// ---------------- prep kernels -----------------------------------------------
__global__ void k_h_wkT(const float* __restrict__ Wk, __half* __restrict__ dst) {
    __shared__ float t[32][33];
    int bk = blockIdx.x * 32, bn = blockIdx.y * 32;
    int tx = threadIdx.x, ty = threadIdx.y;
    #pragma unroll
    for (int i = 0; i < 32; i += 8)
        t[ty + i][tx] = Wk[(bn + ty + i) * DIM + bk + tx];
    __syncthreads();
    #pragma unroll
    for (int i = 0; i < 32; i += 8)
        dst[(size_t)(bk + ty + i) * DIM + bn + tx] = __float2half(t[tx][ty + i]);
}
__global__ void k_h_wg(const float* __restrict__ Wg, __half* __restrict__ dst, int N) {
    int i = blockIdx.x * blockDim.x + threadIdx.x;
    if (i < 2 * DIM * DIM) dst[i] = __float2half(Wg[i]);
    if (i < N) g_cnt[i] = 0;
    if (i == 0) g_ovf_cnt = 0;
}
// prev fp32 -> fp16 image (one thread per 8 elements)
__global__ void k_h_prev(const float* __restrict__ prev, __half* __restrict__ dst, int total8) {
    int i = blockIdx.x * blockDim.x + threadIdx.x;
    if (i >= total8) return;
    const float4* p = (const float4*)prev + (size_t)2 * i;
    float4 a = __ldcs(p), b = __ldcs(p + 1);
    __half2 h0 = __floats2half2_rn(a.x, a.y);
    __half2 h1 = __floats2half2_rn(a.z, a.w);
    __half2 h2 = __floats2half2_rn(b.x, b.y);
    __half2 h3 = __floats2half2_rn(b.z, b.w);
    uint4 o = make_uint4(*(uint32_t*)&h0, *(uint32_t*)&h1, *(uint32_t*)&h2, *(uint32_t*)&h3);
    ((uint4*)dst)[i] = o;
}

// ---------------- bucketing --------------------------------------------------
__global__ void k_bucket(const int* __restrict__ idx, int E) {
    int e = blockIdx.x * blockDim.x + threadIdx.x;
    if (e >= E) return;
    int n = __ldg(idx + e);
    int r = atomicAdd(&g_cnt[n], 1);
    if (r < BCAP) g_bucket[(size_t)n * BCAP + r] = e;
    else          g_ovf[atomicAdd(&g_ovf_cnt, 1)] = e;
}

// ---------------- edge phase: warp/node, normalize-early, fp16 store ---------
__global__ __launch_bounds__(256) void k_edge_n(const float* __restrict__ x,
                                                const int* __restrict__ idx, int N) {
    int warp = threadIdx.x >> 5, lane = threadIdx.x & 31;
    int n = blockIdx.x * 8 + warp;
    if (n >= N) return;

    int c_full = g_cnt[n];
    int c = c_full < BCAP ? c_full : BCAP;
    uint2* cbh0 = (uint2*)(g_combh + (size_t)n * DIM + (size_t)lane * 4);
    uint2* cbh1 = (uint2*)(g_combh + (size_t)n * DIM + 128 + (size_t)lane * 4);

    if (c_full == 0) {
        uint2 z = make_uint2(0u, 0u);
        *cbh0 = z; *cbh1 = z;
        return;
    }

    const uint2* vp = (const uint2*)(g_vh + (size_t)n * DIM);
    uint2 h0 = vp[lane], h1 = vp[lane + 32];
    float2 v0 = __half22float2(*(__half2*)&h0.x);
    float2 v1 = __half22float2(*(__half2*)&h0.y);
    float2 v2 = __half22float2(*(__half2*)&h1.x);
    float2 v3 = __half22float2(*(__half2*)&h1.y);
    float bqn = g_bq[n];

    const int* bkt = g_bucket + (size_t)n * BCAP;
    int e = __ldg(bkt);
    const float4* xp = (const float4*)(x + (size_t)e * DIM);
    float4 a0 = __ldcs(xp + lane);
    float4 a1 = __ldcs(xp + lane + 32);

    float den = 0.f;
    float4 acc0 = make_float4(0.f, 0.f, 0.f, 0.f);
    float4 acc1 = make_float4(0.f, 0.f, 0.f, 0.f);

    for (int j = 0; j < c; j++) {
        float4 b0, b1;
        if (j + 1 < c) {
            int e2 = __ldg(bkt + j + 1);
            const float4* xp2 = (const float4*)(x + (size_t)e2 * DIM);
            b0 = __ldcs(xp2 + lane);
            b1 = __ldcs(xp2 + lane + 32);
        }
        float s = a0.x * v0.x + a0.y * v0.y + a0.z * v1.x + a0.w * v1.y
                + a1.x * v2.x + a1.y * v2.y + a1.z * v3.x + a1.w * v3.y;
        #pragma unroll
        for (int o = 16; o; o >>= 1) s += __shfl_xor_sync(0xffffffffu, s, o);
        float ex = expf((s + bqn) * 0.0625f);
        den += ex;
        acc0.x += ex * a0.x; acc0.y += ex * a0.y; acc0.z += ex * a0.z; acc0.w += ex * a0.w;
        acc1.x += ex * a1.x; acc1.y += ex * a1.y; acc1.z += ex * a1.z; acc1.w += ex * a1.w;
        a0 = b0; a1 = b1;
    }

    if (c_full > BCAP) {
        int t = g_ovf_cnt;
        for (int i = 0; i < t; i++) {
            int e2 = g_ovf[i];
            if (__ldg(idx + e2) != n) continue;
            const float4* xp2 = (const float4*)(x + (size_t)e2 * DIM);
            float4 c0 = xp2[lane], c1 = xp2[lane + 32];
            float s = c0.x * v0.x + c0.y * v0.y + c0.z * v1.x + c0.w * v1.y
                    + c1.x * v2.x + c1.y * v2.y + c1.z * v3.x + c1.w * v3.y;
            #pragma unroll
            for (int o = 16; o; o >>= 1) s += __shfl_xor_sync(0xffffffffu, s, o);
            float ex = expf((s + bqn) * 0.0625f);
            den += ex;
            acc0.x += ex * c0.x; acc0.y += ex * c0.y; acc0.z += ex * c0.z; acc0.w += ex * c0.w;
            acc1.x += ex * c1.x; acc1.y += ex * c1.y; acc1.z += ex * c1.z; acc1.w += ex * c1.w;
        }
    }

    float inv = 1.f / fmaxf(den, 1e-9f);
    __half2 p0 = __floats2half2_rn(acc0.x * inv, acc0.y * inv);
    __half2 p1 = __floats2half2_rn(acc0.z * inv, acc0.w * inv);
    __half2 p2 = __floats2half2_rn(acc1.x * inv, acc1.y * inv);
    __half2 p3 = __floats2half2_rn(acc1.z * inv, acc1.w * inv);
    *cbh0 = make_uint2(*(uint32_t*)&p0, *(uint32_t*)&p1);
    *cbh1 = make_uint2(*(uint32_t*)&p2, *(uint32_t*)&p3);
}

// ---------------- fp16 tensor-core GEMM: all-cp.async A, 2 CTAs/SM -----------
#define BM 64
#define BN 256
#define BK 32
#define ASTRH 40
#define BSTRH 264

template<int KT, bool GATE>
__global__ __launch_bounds__(256, 2) void k_gemm_h(const float* __restrict__ Aprev,
                                                   const float* __restrict__ bias,
                                                   float* __restrict__ out, int M) {
    __shared__ __half As[2][BM * ASTRH];
    __shared__ __half Bs[2][BK * BSTRH];
    __shared__ float  bks[DIM];

    const int tid  = threadIdx.x;
    const int lane = tid & 31;
    const int g    = lane >> 2;
    const int tg   = lane & 3;
    const int wid  = tid >> 5;
    const int wR   = (wid & 1) * 32;
    const int wCat = (wid >> 1) * 8;
    const int bm   = blockIdx.x * BM;
    const int lj   = lane >> 3;
    const int lr   = lane & 7;

    if (tid < 64) *(float4*)&bks[tid * 4] = *(const float4*)(bias + tid * 4);
    __syncthreads();

    float c[2][8][4];
    #pragma unroll
    for (int mi = 0; mi < 2; mi++)
        #pragma unroll
        for (int ni = 0; ni < 8; ni++)
            #pragma unroll
            for (int q = 0; q < 4; q++) c[mi][ni][q] = 0.f;

    // A stage: pure cp.async from fp16 image (g_ph or g_combh)
    auto stage = [&](int it, int buf) {
        const __half* asrc; int k0;
        if (GATE) {
            if (it < 8) { asrc = (const __half*)g_combh; k0 = it * 32; }
            else        { asrc = (const __half*)g_ph;    k0 = (it - 8) * 32; }
        } else {
            asrc = (const __half*)g_ph; k0 = it * 32;
        }
        {   // A: 64 rows x 32 halves = 256 x 16B, one per thread
            int row = tid >> 2, c8 = (tid & 3) * 8;
            int gr = bm + row; if (gr >= M) gr = M - 1;
            cp_async16(smem_u32(&As[buf][row * ASTRH + c8]),
                       asrc + (size_t)gr * DIM + k0 + c8);
        }
        const __half* bh = GATE ? (const __half*)g_bh_g : (const __half*)g_bh_v;
        int kb = GATE ? (it < 8 ? 256 + it * 32 : (it - 8) * 32) : it * 32;
        #pragma unroll
        for (int j = 0; j < 4; j++) {
            int seg = tid + j * 256;
            int kr = seg >> 5, c8 = (seg & 31) * 8;
            cp_async16(smem_u32(&Bs[buf][kr * BSTRH + c8]),
                       bh + (size_t)(kb + kr) * DIM + c8);
        }
        cp_commit();
    };

    stage(0, 0);

    float bqacc = 0.f;
    const int bq_row = tid >> 2;
    const int bq_q   = tid & 3;

    #pragma unroll 1
    for (int it = 0; it < KT; it++) {
        int buf = it & 1;
        if (it + 1 < KT) {
            stage(it + 1, (it + 1) & 1);
            asm volatile("cp.async.wait_group 1;\n" ::: "memory");
        } else {
            asm volatile("cp.async.wait_group 0;\n" ::: "memory");
        }
        __syncthreads();

        const __half* Ab = As[buf];
        const __half* Bb = Bs[buf];
        #pragma unroll
        for (int ks = 0; ks < BK; ks += 16) {
            uint32_t a[2][4];
            #pragma unroll
            for (int mi = 0; mi < 2; mi++) {
                uint32_t ad = smem_u32(&Ab[(wR + mi * 16 + (lj & 1) * 8 + lr) * ASTRH
                                           + ks + (lj >> 1) * 8]);
                ldsm_x4(a[mi], ad);
            }
            #pragma unroll
            for (int nn = 0; nn < 4; nn++) {
                uint32_t b[4];
                uint32_t bd = smem_u32(&Bb[(ks + (lj & 1) * 8 + lr) * BSTRH
                                           + (wCat + nn * 2 + (lj >> 1)) * 8]);
                ldsm_x4_t(b, bd);
                #pragma unroll
                for (int mi = 0; mi < 2; mi++) {
                    mma_f16(c[mi][nn * 2 + 0], a[mi], b[0], b[1]);
                    mma_f16(c[mi][nn * 2 + 1], a[mi], b[2], b[3]);
                }
            }
        }

        if (!GATE) {
            float s = 0.f;
            #pragma unroll
            for (int j = 0; j < 8; j++)
                s += __half2float(Ab[bq_row * ASTRH + bq_q * 8 + j])
                   * bks[it * 32 + bq_q * 8 + j];
            bqacc += s;
        }
        __syncthreads();
    }

    if (!GATE) {
        bqacc += __shfl_xor_sync(0xffffffffu, bqacc, 1);
        bqacc += __shfl_xor_sync(0xffffffffu, bqacc, 2);
        if (bq_q == 0 && bm + bq_row < M) g_bq[bm + bq_row] = bqacc;
    }

    #pragma unroll
    for (int mi = 0; mi < 2; mi++) {
        #pragma unroll
        for (int half = 0; half < 2; half++) {
            int r = bm + wR + mi * 16 + g + half * 8;
            if (r >= M) continue;
            #pragma unroll
            for (int ni = 0; ni < 8; ni++) {
                int cc = wCat * 8 + ni * 8 + tg * 2;
                float v0 = c[mi][ni][half * 2 + 0];
                float v1 = c[mi][ni][half * 2 + 1];
                if (GATE) {
                    float2 pv = *(const float2*)(Aprev + (size_t)r * DIM + cc);
                    uint32_t ch = *(const uint32_t*)(g_combh + (size_t)r * DIM + cc);
                    float2 cv = __half22float2(*(__half2*)&ch);
                    float g0 = 1.f / (1.f + expf(-(v0 + bks[cc])));
                    float g1 = 1.f / (1.f + expf(-(v1 + bks[cc + 1])));
                    float2 o;
                    o.x = g0 * pv.x + (1.f - g0) * cv.x;
                    o.y = g1 * pv.y + (1.f - g1) * cv.y;
                    *(float2*)(out + (size_t)r * DIM + cc) = o;
                } else {
                    __half2 hv = __floats2half2_rn(v0, v1);
                    *(uint32_t*)(g_vh + (size_t)r * DIM + cc) = *(uint32_t*)&hv;
                }
            }
        }
    }
}

// ---------------- launch ------------------------------------------------------
extern "C" void kernel_launch(void* const* d_in, const int* in_sizes, int n_in,
                              void* d_out, int out_size) {
    const float* x    = (const float*)d_in[0];
    const float* prev = (const float*)d_in[1];
    const float* Wk   = (const float*)d_in[2];
    const float* bk   = (const float*)d_in[3];
    const float* Wg   = (const float*)d_in[4];
    const float* bg   = (const float*)d_in[5];
    const int*   idx  = (const int*)d_in[6];
    float* out = (float*)d_out;

    int Dv = in_sizes[3];            // 256
    int E  = in_sizes[0] / Dv;
    int N  = in_sizes[1] / Dv;

    __half* bhv = nullptr; cudaGetSymbolAddress((void**)&bhv, g_bh_v);
    __half* bhg = nullptr; cudaGetSymbolAddress((void**)&bhg, g_bh_g);
    __half* ph  = nullptr; cudaGetSymbolAddress((void**)&ph,  g_ph);
    k_h_wkT<<<dim3(8, 8), dim3(32, 8)>>>(Wk, bhv);
    k_h_wg<<<(2 * DIM * DIM + 255) / 256, 256>>>(Wg, bhg, N);
    int total8 = N * (DIM / 8);
    k_h_prev<<<(total8 + 255) / 256, 256>>>(prev, ph, total8);
    k_bucket<<<(E + 255) / 256, 256>>>(idx, E);

    int gb = (N + BM - 1) / BM;
    k_gemm_h<8, false><<<gb, 256>>>(prev, bk, nullptr, N);

    k_edge_n<<<(N + 7) / 8, 256>>>(x, idx, N);

    k_gemm_h<16, true><<<gb, 256>>>(prev, bg, out, N);
}

// round 17
// speedup vs baseline: 1.1852x; 1.0308x over previous
#include <cuda_runtime.h>
#include <cuda_fp16.h>
#include <math.h>
#include <stdint.h>

#define DIM   256
#define MAXN  100000
#define MAXE  500000
#define BCAP  64

// ---------------- scratch ---------------------------------------------------
__device__ __half g_vh[(size_t)MAXN * DIM];     // v in fp16
__device__ __half g_combh[(size_t)MAXN * DIM];  // NORMALIZED comb in fp16
__device__ float  g_bq[MAXN];
__device__ __half g_bh_v[DIM * DIM];            // Wk^T as fp16, [k][n]
__device__ __half g_bh_g[2 * DIM * DIM];        // Wg   as fp16, [k][n]
__device__ int    g_cnt[MAXN];
__device__ int    g_bucket[(size_t)MAXN * BCAP];
__device__ int    g_ovf[MAXE];
__device__ int    g_ovf_cnt;

// ---------------- helpers ---------------------------------------------------
__device__ __forceinline__ uint32_t smem_u32(const void* p) {
    uint32_t a;
    asm("{ .reg .u64 t; cvta.to.shared.u64 t, %1; cvt.u32.u64 %0, t; }" : "=r"(a) : "l"(p));
    return a;
}
__device__ __forceinline__ void cp_async16(uint32_t saddr, const void* gaddr) {
    asm volatile("cp.async.ca.shared.global [%0], [%1], 16;\n" :: "r"(saddr), "l"(gaddr));
}
__device__ __forceinline__ void cp_commit() {
    asm volatile("cp.async.commit_group;\n");
}
__device__ __forceinline__ void ldsm_x4(uint32_t r[4], uint32_t addr) {
    asm volatile("ldmatrix.sync.aligned.m8n8.x4.shared.b16 {%0,%1,%2,%3}, [%4];"
                 : "=r"(r[0]), "=r"(r[1]), "=r"(r[2]), "=r"(r[3]) : "r"(addr));
}
__device__ __forceinline__ void ldsm_x4_t(uint32_t r[4], uint32_t addr) {
    asm volatile("ldmatrix.sync.aligned.m8n8.x4.trans.shared.b16 {%0,%1,%2,%3}, [%4];"
                 : "=r"(r[0]), "=r"(r[1]), "=r"(r[2]), "=r"(r[3]) : "r"(addr));
}
__device__ __forceinline__ void mma_f16(float c[4], const uint32_t a[4], uint32_t b0, uint32_t b1) {
    asm volatile(
        "mma.sync.aligned.m16n8k16.row.col.f32.f16.f16.f32 "
        "{%0,%1,%2,%3}, {%4,%5,%6,%7}, {%8,%9}, {%0,%1,%2,%3};"
        : "+f"(c[0]), "+f"(c[1]), "+f"(c[2]), "+f"(c[3])
        : "r"(a[0]), "r"(a[1]), "r"(a[2]), "r"(a[3]), "r"(b0), "r"(b1));
}

// ---------------- prep kernels -----------------------------------------------
__global__ void k_h_wkT(const float* __restrict__ Wk, __half* __restrict__ dst) {
    __shared__ float t[32][33];
    int bk = blockIdx.x * 32, bn = blockIdx.y * 32;
    int tx = threadIdx.x, ty = threadIdx.y;
    #pragma unroll
    for (int i = 0; i < 32; i += 8)
        t[ty + i][tx] = Wk[(bn + ty + i) * DIM + bk + tx];
    __syncthreads();
    #pragma unroll
    for (int i = 0; i < 32; i += 8)
        dst[(size_t)(bk + ty + i) * DIM + bn + tx] = __float2half(t[tx][ty + i]);
}
__global__ void k_h_wg(const float* __restrict__ Wg, __half* __restrict__ dst, int N) {
    int i = blockIdx.x * blockDim.x + threadIdx.x;
    if (i < 2 * DIM * DIM) dst[i] = __float2half(Wg[i]);
    if (i < N) g_cnt[i] = 0;
    if (i == 0) g_ovf_cnt = 0;
}

// ---------------- bucketing: 2 edges/thread (double the atomic MLP) ----------
__global__ void k_bucket(const int* __restrict__ idx, int E) {
    int i = blockIdx.x * blockDim.x + threadIdx.x;
    int e0 = 2 * i;
    if (e0 >= E) return;
    int2 nn;
    if (e0 + 1 < E) nn = *(const int2*)(idx + e0);
    else            nn = make_int2(__ldg(idx + e0), -1);
    int r0 = atomicAdd(&g_cnt[nn.x], 1);
    if (r0 < BCAP) g_bucket[(size_t)nn.x * BCAP + r0] = e0;
    else           g_ovf[atomicAdd(&g_ovf_cnt, 1)] = e0;
    if (nn.y >= 0) {
        int r1 = atomicAdd(&g_cnt[nn.y], 1);
        if (r1 < BCAP) g_bucket[(size_t)nn.y * BCAP + r1] = e0 + 1;
        else           g_ovf[atomicAdd(&g_ovf_cnt, 1)] = e0 + 1;
    }
}

// ---------------- edge phase: warp/node, normalize-early, fp16 store ---------
// Bucket ids read in int4 groups -> no per-iteration dependent bkt load.
__global__ __launch_bounds__(256) void k_edge_n(const float* __restrict__ x,
                                                const int* __restrict__ idx, int N) {
    int warp = threadIdx.x >> 5, lane = threadIdx.x & 31;
    int n = blockIdx.x * 8 + warp;
    if (n >= N) return;

    int c_full = g_cnt[n];
    int c = c_full < BCAP ? c_full : BCAP;
    uint2* cbh0 = (uint2*)(g_combh + (size_t)n * DIM + (size_t)lane * 4);
    uint2* cbh1 = (uint2*)(g_combh + (size_t)n * DIM + 128 + (size_t)lane * 4);

    if (c_full == 0) {
        uint2 z = make_uint2(0u, 0u);
        *cbh0 = z; *cbh1 = z;
        return;
    }

    const uint2* vp = (const uint2*)(g_vh + (size_t)n * DIM);
    uint2 h0 = vp[lane], h1 = vp[lane + 32];
    float2 v0 = __half22float2(*(__half2*)&h0.x);
    float2 v1 = __half22float2(*(__half2*)&h0.y);
    float2 v2 = __half22float2(*(__half2*)&h1.x);
    float2 v3 = __half22float2(*(__half2*)&h1.y);
    float bqn = g_bq[n];

    const int* bkt = g_bucket + (size_t)n * BCAP;
    int4 grp = *(const int4*)bkt;                 // first 4 edge ids (256B-aligned)
    int e = grp.x;
    const float4* xp = (const float4*)(x + (size_t)e * DIM);
    float4 a0 = __ldcs(xp + lane);
    float4 a1 = __ldcs(xp + lane + 32);

    float den = 0.f;
    float4 acc0 = make_float4(0.f, 0.f, 0.f, 0.f);
    float4 acc1 = make_float4(0.f, 0.f, 0.f, 0.f);

    for (int j = 0; j < c; j++) {
        float4 b0, b1;
        int jn = j + 1;
        if (jn < c) {
            if ((jn & 3) == 0) grp = *(const int4*)(bkt + jn);
            int en = (jn & 3) == 0 ? grp.x
                   : (jn & 3) == 1 ? grp.y
                   : (jn & 3) == 2 ? grp.z : grp.w;
            const float4* xp2 = (const float4*)(x + (size_t)en * DIM);
            b0 = __ldcs(xp2 + lane);
            b1 = __ldcs(xp2 + lane + 32);
        }
        float s = a0.x * v0.x + a0.y * v0.y + a0.z * v1.x + a0.w * v1.y
                + a1.x * v2.x + a1.y * v2.y + a1.z * v3.x + a1.w * v3.y;
        #pragma unroll
        for (int o = 16; o; o >>= 1) s += __shfl_xor_sync(0xffffffffu, s, o);
        float ex = expf((s + bqn) * 0.0625f);
        den += ex;
        acc0.x += ex * a0.x; acc0.y += ex * a0.y; acc0.z += ex * a0.z; acc0.w += ex * a0.w;
        acc1.x += ex * a1.x; acc1.y += ex * a1.y; acc1.z += ex * a1.z; acc1.w += ex * a1.w;
        a0 = b0; a1 = b1;
    }

    if (c_full > BCAP) {                          // rare overflow: scan tiny ovf list
        int t = g_ovf_cnt;
        for (int i = 0; i < t; i++) {
            int e2 = g_ovf[i];
            if (__ldg(idx + e2) != n) continue;
            const float4* xp2 = (const float4*)(x + (size_t)e2 * DIM);
            float4 c0 = xp2[lane], c1 = xp2[lane + 32];
            float s = c0.x * v0.x + c0.y * v0.y + c0.z * v1.x + c0.w * v1.y
                    + c1.x * v2.x + c1.y * v2.y + c1.z * v3.x + c1.w * v3.y;
            #pragma unroll
            for (int o = 16; o; o >>= 1) s += __shfl_xor_sync(0xffffffffu, s, o);
            float ex = expf((s + bqn) * 0.0625f);
            den += ex;
            acc0.x += ex * c0.x; acc0.y += ex * c0.y; acc0.z += ex * c0.z; acc0.w += ex * c0.w;
            acc1.x += ex * c1.x; acc1.y += ex * c1.y; acc1.z += ex * c1.z; acc1.w += ex * c1.w;
        }
    }

    float inv = 1.f / fmaxf(den, 1e-9f);          // normalize early
    __half2 p0 = __floats2half2_rn(acc0.x * inv, acc0.y * inv);
    __half2 p1 = __floats2half2_rn(acc0.z * inv, acc0.w * inv);
    __half2 p2 = __floats2half2_rn(acc1.x * inv, acc1.y * inv);
    __half2 p3 = __floats2half2_rn(acc1.z * inv, acc1.w * inv);
    *cbh0 = make_uint2(*(uint32_t*)&p0, *(uint32_t*)&p1);
    *cbh1 = make_uint2(*(uint32_t*)&p2, *(uint32_t*)&p3);
}

// ---------------- fp16 tensor-core GEMM, BM=64 x BN=256, BK=32 (round-14) ----
#define BM 64
#define BN 256
#define BK 32
#define ASTRH 40
#define BSTRH 264

template<int KT, bool GATE>
__global__ __launch_bounds__(256, 2) void k_gemm_h(const float* __restrict__ Aprev,
                                                   const float* __restrict__ bias,
                                                   float* __restrict__ out, int M) {
    __shared__ __half As[2][BM * ASTRH];
    __shared__ __half Bs[2][BK * BSTRH];
    __shared__ float  bks[DIM];

    const int tid  = threadIdx.x;
    const int lane = tid & 31;
    const int g    = lane >> 2;
    const int tg   = lane & 3;
    const int wid  = tid >> 5;
    const int wR   = (wid & 1) * 32;
    const int wCat = (wid >> 1) * 8;
    const int bm   = blockIdx.x * BM;
    const int lj   = lane >> 3;
    const int lr   = lane & 7;

    if (tid < 64) *(float4*)&bks[tid * 4] = *(const float4*)(bias + tid * 4);
    __syncthreads();

    float c[2][8][4];
    #pragma unroll
    for (int mi = 0; mi < 2; mi++)
        #pragma unroll
        for (int ni = 0; ni < 8; ni++)
            #pragma unroll
            for (int q = 0; q < 4; q++) c[mi][ni][q] = 0.f;

    // GATE it<8: A = g_combh (fp16, normalized) staged via cp.async.
    // otherwise: A = prev (fp32) via LDG-convert-STS (fully hidden under MMA).
    auto a_is_cp = [&](int it) { return GATE && it < 8; };

    auto stageA_cp = [&](int it, int buf) {
        int k0 = it * 32;
        int row = tid >> 2, c8 = (tid & 3) * 8;
        int gr = bm + row; if (gr >= M) gr = M - 1;
        cp_async16(smem_u32(&As[buf][row * ASTRH + c8]),
                   g_combh + (size_t)gr * DIM + k0 + c8);
    };
    auto ldgA = [&](int it, float4 v[2]) {
        int k0 = GATE ? (it - 8) * 32 : it * 32;
        #pragma unroll
        for (int j = 0; j < 2; j++) {
            int seg = tid + j * 256;
            int row = seg >> 3, c4 = (seg & 7) * 4;
            int gr = bm + row; if (gr >= M) gr = M - 1;
            v[j] = *(const float4*)(Aprev + (size_t)gr * DIM + k0 + c4);
        }
    };
    auto stsA = [&](int buf, const float4 v[2]) {
        #pragma unroll
        for (int j = 0; j < 2; j++) {
            int seg = tid + j * 256;
            int row = seg >> 3, c4 = (seg & 7) * 4;
            __half2 h0 = __floats2half2_rn(v[j].x, v[j].y);
            __half2 h1 = __floats2half2_rn(v[j].z, v[j].w);
            uint2 pk = make_uint2(*(uint32_t*)&h0, *(uint32_t*)&h1);
            *(uint2*)&As[buf][row * ASTRH + c4] = pk;
        }
    };
    auto stageB = [&](int it, int buf) {
        const __half* bh = GATE ? (const __half*)g_bh_g : (const __half*)g_bh_v;
        int kb = GATE ? (it < 8 ? 256 + it * 32 : (it - 8) * 32) : it * 32;
        #pragma unroll
        for (int j = 0; j < 4; j++) {
            int seg = tid + j * 256;
            int kr = seg >> 5, c8 = (seg & 31) * 8;
            cp_async16(smem_u32(&Bs[buf][kr * BSTRH + c8]),
                       bh + (size_t)(kb + kr) * DIM + c8);
        }
    };

    float4 vA[2], vN[2];
    bool pendN = false;
    if (a_is_cp(0)) stageA_cp(0, 0);
    else { ldgA(0, vA); stsA(0, vA); }
    stageB(0, 0);
    cp_commit();

    float bqacc = 0.f;
    const int bq_row = tid >> 2;
    const int bq_q   = tid & 3;

    #pragma unroll 1
    for (int it = 0; it < KT; it++) {
        int buf = it & 1;
        if (it + 1 < KT) {
            int nb = (it + 1) & 1;
            if (a_is_cp(it + 1)) { stageA_cp(it + 1, nb); pendN = false; }
            else                 { ldgA(it + 1, vN);      pendN = true;  }
            stageB(it + 1, nb);
            cp_commit();
            asm volatile("cp.async.wait_group 1;\n" ::: "memory");
        } else {
            asm volatile("cp.async.wait_group 0;\n" ::: "memory");
        }
        __syncthreads();

        const __half* Ab = As[buf];
        const __half* Bb = Bs[buf];
        #pragma unroll
        for (int ks = 0; ks < BK; ks += 16) {
            uint32_t a[2][4];
            #pragma unroll
            for (int mi = 0; mi < 2; mi++) {
                uint32_t ad = smem_u32(&Ab[(wR + mi * 16 + (lj & 1) * 8 + lr) * ASTRH
                                           + ks + (lj >> 1) * 8]);
                ldsm_x4(a[mi], ad);
            }
            #pragma unroll
            for (int nn = 0; nn < 4; nn++) {
                uint32_t b[4];
                uint32_t bd = smem_u32(&Bb[(ks + (lj & 1) * 8 + lr) * BSTRH
                                           + (wCat + nn * 2 + (lj >> 1)) * 8]);
                ldsm_x4_t(b, bd);
                #pragma unroll
                for (int mi = 0; mi < 2; mi++) {
                    mma_f16(c[mi][nn * 2 + 0], a[mi], b[0], b[1]);
                    mma_f16(c[mi][nn * 2 + 1], a[mi], b[2], b[3]);
                }
            }
        }

        if (!GATE) {
            float s = 0.f;
            #pragma unroll
            for (int j = 0; j < 8; j++)
                s += __half2float(Ab[bq_row * ASTRH + bq_q * 8 + j])
                   * bks[it * 32 + bq_q * 8 + j];
            bqacc += s;
        }

        if (it + 1 < KT && pendN) stsA((it + 1) & 1, vN);
        __syncthreads();
    }

    if (!GATE) {
        bqacc += __shfl_xor_sync(0xffffffffu, bqacc, 1);
        bqacc += __shfl_xor_sync(0xffffffffu, bqacc, 2);
        if (bq_q == 0 && bm + bq_row < M) g_bq[bm + bq_row] = bqacc;
    }

    #pragma unroll
    for (int mi = 0; mi < 2; mi++) {
        #pragma unroll
        for (int half = 0; half < 2; half++) {
            int r = bm + wR + mi * 16 + g + half * 8;
            if (r >= M) continue;
            #pragma unroll
            for (int ni = 0; ni < 8; ni++) {
                int cc = wCat * 8 + ni * 8 + tg * 2;
                float v0 = c[mi][ni][half * 2 + 0];
                float v1 = c[mi][ni][half * 2 + 1];
                if (GATE) {
                    float2 pv = *(const float2*)(Aprev + (size_t)r * DIM + cc);
                    uint32_t ch = *(const uint32_t*)(g_combh + (size_t)r * DIM + cc);
                    float2 cv = __half22float2(*(__half2*)&ch);
                    float g0 = 1.f / (1.f + expf(-(v0 + bks[cc])));
                    float g1 = 1.f / (1.f + expf(-(v1 + bks[cc + 1])));
                    float2 o;
                    o.x = g0 * pv.x + (1.f - g0) * cv.x;
                    o.y = g1 * pv.y + (1.f - g1) * cv.y;
                    *(float2*)(out + (size_t)r * DIM + cc) = o;
                } else {
                    __half2 hv = __floats2half2_rn(v0, v1);
                    *(uint32_t*)(g_vh + (size_t)r * DIM + cc) = *(uint32_t*)&hv;
                }
            }
        }
    }
}

// ---------------- launch ------------------------------------------------------
extern "C" void kernel_launch(void* const* d_in, const int* in_sizes, int n_in,
                              void* d_out, int out_size) {
    const float* x    = (const float*)d_in[0];
    const float* prev = (const float*)d_in[1];
    const float* Wk   = (const float*)d_in[2];
    const float* bk   = (const float*)d_in[3];
    const float* Wg   = (const float*)d_in[4];
    const float* bg   = (const float*)d_in[5];
    const int*   idx  = (const int*)d_in[6];
    float* out = (float*)d_out;

    int Dv = in_sizes[3];            // 256
    int E  = in_sizes[0] / Dv;
    int N  = in_sizes[1] / Dv;

    __half* bhv = nullptr; cudaGetSymbolAddress((void**)&bhv, g_bh_v);
    __half* bhg = nullptr; cudaGetSymbolAddress((void**)&bhg, g_bh_g);
    k_h_wkT<<<dim3(8, 8), dim3(32, 8)>>>(Wk, bhv);
    k_h_wg<<<(2 * DIM * DIM + 255) / 256, 256>>>(Wg, bhg, N);
    k_bucket<<<((E + 1) / 2 + 255) / 256, 256>>>(idx, E);

    int gb = (N + BM - 1) / BM;
    k_gemm_h<8, false><<<gb, 256>>>(prev, bk, nullptr, N);

    k_edge_n<<<(N + 7) / 8, 256>>>(x, idx, N);

    k_gemm_h<16, true><<<gb, 256>>>(prev, bg, out, N);
}